// round 8
// baseline (speedup 1.0000x reference)
#include <cuda_runtime.h>
#include <math.h>

#define XS 540
#define YS 540
#define BATCH 4
#define NBOX 64
#define TILE 32
#define TXN 17
#define TYN 17
#define NBLOCKS (TXN*TYN*BATCH)
#define FIXSCALE 67108864.0   // 2^26

__device__ unsigned long long g_acc[BATCH][2];
__device__ unsigned int g_done;

struct BoxC { float cx, cy, c, s, hw, hl, hv; };

__global__ void __launch_bounds__(256)
hm_loss_fused_kernel(const float* __restrict__ logits,
                     const float* __restrict__ boxes,
                     const float* __restrict__ hm,
                     float* __restrict__ out)
{
    __shared__ BoxC bc[NBOX];
    __shared__ unsigned int sm_mask[2];
    __shared__ float ws[8];
    __shared__ int   wc[8];

    const int b    = blockIdx.z;
    const int tid  = threadIdx.x;
    const int lane = tid & 31;
    const int wrp  = tid >> 5;

    // ---- box loads FIRST (they feed the barrier everyone waits on) ----
    float p0, p1, p3, p4, p5, p6;
    if (tid < NBOX) {
        const float* p = boxes + (b * NBOX + tid) * 7;
        p0 = p[0]; p1 = p[1]; p3 = p[3]; p4 = p[4]; p5 = p[5]; p6 = p[6];
    }

    // ---- pixel prefetch: thread = 4 contiguous x px in one row ----
    const int x4 = blockIdx.x * TILE + (lane & 7) * 4;
    const int y  = blockIdx.y * TILE + (tid >> 3);
    const bool ok = (x4 + 3 < XS) && (y < YS);

    float4 xl4 = make_float4(0.f, 0.f, 0.f, 0.f);
    float4 hh4 = make_float4(0.f, 0.f, 0.f, 0.f);
    if (ok) {
        const int idx = (b * YS + y) * XS + x4;
        xl4 = *reinterpret_cast<const float4*>(logits + idx);
        hh4 = *reinterpret_cast<const float4*>(hm + idx);
    }

    // ---- box transform + cull + ballot ----
    if (tid < NBOX) {
        BoxC v;
        v.cx = (p0 + 54.0f) * 5.0f;
        v.cy = (p1 + 54.0f) * 5.0f;
        v.hw = p3 * 2.5f;
        v.hl = p4 * 2.5f;
        float sn, cn;
        __sincosf(p6, &sn, &cn);
        v.c  = cn;           // cos(-theta)
        v.s  = -sn;          // sin(-theta)
        v.hv = p5 * 0.2f;
        bc[tid] = v;

        const float ex = fabsf(v.c) * v.hw + fabsf(v.s) * v.hl;
        const float ey = fabsf(v.s) * v.hw + fabsf(v.c) * v.hl;
        const float tx0 = (float)(blockIdx.x * TILE);
        const float ty0 = (float)(blockIdx.y * TILE);
        const bool hit = (v.cx - ex <= tx0 + (float)(TILE - 1)) && (v.cx + ex >= tx0) &&
                         (v.cy - ey <= ty0 + (float)(TILE - 1)) && (v.cy + ey >= ty0);
        const unsigned int m = __ballot_sync(0xffffffffu, hit);
        if (lane == 0) sm_mask[wrp] = m;
    }
    __syncthreads();

    const unsigned long long mask =
        ((unsigned long long)sm_mask[1] << 32) | (unsigned long long)sm_mask[0];

    // ---- raster: last box wins, sticky first hit scanning high->low ----
    float gt[4] = {0.f, 0.f, 0.f, 0.f};
    if (ok) {
        const float fx0 = (float)x4;
        const float fy  = (float)y;
        bool fnd[4] = {false, false, false, false};
        unsigned long long mm = mask;
        while (mm) {
            const int i = 63 - __clzll(mm);
            mm ^= (1ull << i);
            const BoxC v = bc[i];
            const float dx = fx0 - v.cx;
            const float dy = fy - v.cy;
            float lx = dx * v.c - dy * v.s;
            float ly = dx * v.s + dy * v.c;
            #pragma unroll
            for (int j = 0; j < 4; j++) {
                const bool inside = (fabsf(lx) <= v.hw) && (fabsf(ly) <= v.hl);
                if (inside && !fnd[j]) { gt[j] = v.hv; fnd[j] = true; }
                lx += v.c;
                ly += v.s;
            }
        }
    }

    // ---- loss: branch-free, single combined accumulator ----
    float sc = 0.0f;
    int   cv = 0;
    const float* xvp = &xl4.x;
    const float* hhp = &hh4.x;
    #pragma unroll
    for (int j = 0; j < 4; j++) {
        const float g  = gt[j];
        const bool pos = (g > 0.0f);
        const bool valid = ok && (pos || (hhp[j] > 0.0f));
        const float xl = xvp[j];

        const float weight = pos ? 5.0f : 0.1f;
        const float e  = __expf(-fabsf(xl));          // MUFU EX2
        const float d  = 1.0f + e;
        const float bce = fmaxf(xl, 0.0f) - xl * g + __logf(d);  // MUFU LG2
        const float rd = __fdividef(1.0f, d);         // MUFU RCP (correct domain)
        const float p  = (xl >= 0.0f) ? rd : e * rd;  // sigmoid
        const float u  = fmaf(p, 1.0f - 2.0f * g, g); // 1 - p_t
        const float aw = 0.75f - 0.5f * g;
        const float contrib = weight * bce * fmaf(u * u, aw, 1.0f);
        sc += valid ? contrib : 0.0f;
        cv += valid ? 1 : 0;
    }

    const int cnt = __reduce_add_sync(0xffffffffu, cv);
    #pragma unroll
    for (int st = 16; st > 0; st >>= 1)
        sc += __shfl_xor_sync(0xffffffffu, sc, st);
    if (lane == 0) { ws[wrp] = sc; wc[wrp] = cnt; }
    __syncthreads();

    // ---- final combine in warp 0 (8 lanes, 3 shuffles) ----
    if (tid < 8) {
        float t1 = ws[tid];
        int   t0 = wc[tid];
        #pragma unroll
        for (int st = 4; st > 0; st >>= 1)
            t1 += __shfl_xor_sync(0x000000ffu, t1, st);
        t0 = __reduce_add_sync(0x000000ffu, t0);

        if (tid == 0) {
            atomicAdd(&g_acc[b][0], (unsigned long long)t0);
            atomicAdd(&g_acc[b][1], (unsigned long long)llrint((double)t1 * FIXSCALE));
            __threadfence();

            const unsigned int ticket = atomicAdd(&g_done, 1u);
            if (ticket == NBLOCKS - 1) {
                float total = 0.0f, ns = 0.0f;
                #pragma unroll
                for (int bb = 0; bb < BATCH; bb++) {
                    const double cnt_b = (double)g_acc[bb][0];
                    if (cnt_b > 0.0) {
                        const double s = (double)g_acc[bb][1] / FIXSCALE;
                        total += (float)(0.5 * s / fmax(cnt_b, 1.0));
                        ns += 1.0f;
                    }
                }
                out[0] = (ns > 0.0f) ? (total / fmaxf(ns, 1.0f)) : total;
                #pragma unroll
                for (int bb = 0; bb < BATCH; bb++) {
                    g_acc[bb][0] = 0ull; g_acc[bb][1] = 0ull;
                }
                __threadfence();
                g_done = 0u;
            }
        }
    }
}

extern "C" void kernel_launch(void* const* d_in, const int* in_sizes, int n_in,
                              void* d_out, int out_size)
{
    const float* arrs[3] = { (const float*)d_in[0],
                             (const float*)d_in[1],
                             (const float*)d_in[2] };
    const float* logits = arrs[0];
    const float* boxes  = arrs[1];
    const float* hmap   = arrs[2];
    if (n_in >= 3) {
        int bi = -1;
        for (int i = 0; i < 3; i++)
            if (in_sizes[i] == BATCH * NBOX * 7) { bi = i; break; }
        if (bi >= 0) {
            boxes = arrs[bi];
            int o0 = -1, o1 = -1;
            for (int i = 0; i < 3; i++) {
                if (i == bi) continue;
                if (o0 < 0) o0 = i; else o1 = i;
            }
            logits = arrs[o0];
            hmap   = arrs[o1];
        }
    }

    dim3 block(256, 1, 1);
    dim3 grid(TXN, TYN, BATCH);
    hm_loss_fused_kernel<<<grid, block>>>(logits, boxes, hmap, (float*)d_out);
}